// round 4
// baseline (speedup 1.0000x reference)
#include <cuda_runtime.h>
#include <cuda_bf16.h>
#include <math.h>
#include <stdint.h>

#define M_ROWS 36928   // B*T = 64*577
#define E_DIM  768
#define H_DIM  64
#define T_LEN  577
#define B_SZ   64
#define GW     24

// scratch (static device arrays; no allocation)
__device__ float g_q[M_ROWS * H_DIM];
__device__ float g_k[M_ROWS * H_DIM];
__device__ float g_v[M_ROWS * H_DIM];
// concatenated transposed weights, split bf16: [n=192][k=768]
__device__ __nv_bfloat16 g_wcat_hi[192 * E_DIM];
__device__ __nv_bfloat16 g_wcat_lo[192 * E_DIM];

__device__ __forceinline__ uint32_t smem_u32(const void* p) {
    uint32_t a;
    asm("{ .reg .u64 t; cvta.to.shared.u64 t, %1; cvt.u32.u64 %0, t; }" : "=r"(a) : "l"(p));
    return a;
}
__device__ __forceinline__ void ldsm_x4(uint32_t* r, uint32_t addr) {
    asm volatile("ldmatrix.sync.aligned.m8n8.x4.shared.b16 {%0,%1,%2,%3}, [%4];"
                 : "=r"(r[0]), "=r"(r[1]), "=r"(r[2]), "=r"(r[3]) : "r"(addr));
}
__device__ __forceinline__ void mma_bf16(float* d, const uint32_t* a, const uint32_t* b) {
    asm volatile(
        "mma.sync.aligned.m16n8k16.row.col.f32.bf16.bf16.f32 "
        "{%0,%1,%2,%3}, {%4,%5,%6,%7}, {%8,%9}, {%0,%1,%2,%3};"
        : "+f"(d[0]), "+f"(d[1]), "+f"(d[2]), "+f"(d[3])
        : "r"(a[0]), "r"(a[1]), "r"(a[2]), "r"(a[3]), "r"(b[0]), "r"(b[1]));
}
__device__ __forceinline__ uint32_t packbf(__nv_bfloat16 a, __nv_bfloat16 b) {
    uint16_t ua = *(uint16_t*)&a, ub = *(uint16_t*)&b;
    return (uint32_t)ua | ((uint32_t)ub << 16);
}

// ---------------------------------------------------------------------------
// Kernel 0: weight prep — wcat[n][k] = w_{q,k,v}[k][n%64], split into bf16 hi/lo
// ---------------------------------------------------------------------------
__global__ void prep_w_kernel(const float* __restrict__ w_q, const float* __restrict__ w_k,
                              const float* __restrict__ w_v)
{
    int idx = blockIdx.x * blockDim.x + threadIdx.x;
    if (idx >= 192 * E_DIM) return;
    int n = idx / E_DIM, k = idx % E_DIM;
    const float* w = (n < 64) ? w_q : (n < 128) ? w_k : w_v;
    float v = w[k * H_DIM + (n & 63)];
    __nv_bfloat16 hi = __float2bfloat16(v);
    __nv_bfloat16 lo = __float2bfloat16(v - __bfloat162float(hi));
    g_wcat_hi[idx] = hi;
    g_wcat_lo[idx] = lo;
}

// ---------------------------------------------------------------------------
// Kernel 1: split-bf16 mma.sync QKV GEMM + fused LayerNorm epilogue
// grid = 577 (M tiles of 64), 256 threads = 8 warps (2M x 4N), warp tile 32x48
// D[64,192] = X[64,768] @ Wcat^T, hi*hi + hi*lo + lo*hi into fp32 acc
// ---------------------------------------------------------------------------
#define GK 64
#define NCHUNK (E_DIM / GK)
#define AS 144                     // smem row stride bytes (72 bf16)
#define SM_A_HI 0
#define SM_A_LO (SM_A_HI + 64 * AS)        //  9216
#define SM_B_HI (SM_A_LO + 64 * AS)        // 18432
#define SM_B_LO (SM_B_HI + 192 * AS)       // 46080
#define SM_TOTAL (SM_B_LO + 192 * AS)      // 73728
#define STG_S 201                  // epilogue stage stride (floats)

__global__ __launch_bounds__(256, 2) void qkv_mma_kernel(
    const float* __restrict__ x,
    const float* __restrict__ q_gamma, const float* __restrict__ q_beta,
    const float* __restrict__ k_gamma, const float* __restrict__ k_beta)
{
    extern __shared__ char smc[];
    const uint32_t sb = smem_u32(smc);
    const int tid  = threadIdx.x;
    const int wid  = tid >> 5;
    const int lane = tid & 31;
    const int wm   = wid >> 2;          // 0..1 -> M offset *32
    const int wn   = wid & 3;           // 0..3 -> N offset *48
    const int m0   = blockIdx.x * 64;

    // per-lane ldmatrix base offsets
    const uint32_t aOff = (uint32_t)((wm * 32 + (lane & 15)) * AS + (lane >> 4) * 16);
    const uint32_t bOff = (uint32_t)((wn * 48 + ((lane >> 4) << 3) + (lane & 7)) * AS
                                     + ((lane >> 3) & 1) * 16);

    float acc[2][6][4];
#pragma unroll
    for (int i = 0; i < 2; i++)
#pragma unroll
        for (int j = 0; j < 6; j++)
#pragma unroll
            for (int c = 0; c < 4; c++) acc[i][j][c] = 0.f;

    for (int ch = 0; ch < NCHUNK; ch++) {
        const int k0 = ch * GK;
        // A chunk: x fp32 -> bf16 hi/lo (64 rows x 64 cols)
#pragma unroll
        for (int it = 0; it < 4; it++) {
            int i = tid + it * 256;         // 0..1023
            int r = i >> 4, col = (i & 15) * 4;
            float4 v = *(const float4*)&x[(size_t)(m0 + r) * E_DIM + k0 + col];
            __nv_bfloat16 h0 = __float2bfloat16(v.x), h1 = __float2bfloat16(v.y);
            __nv_bfloat16 h2 = __float2bfloat16(v.z), h3 = __float2bfloat16(v.w);
            __nv_bfloat16 l0 = __float2bfloat16(v.x - __bfloat162float(h0));
            __nv_bfloat16 l1 = __float2bfloat16(v.y - __bfloat162float(h1));
            __nv_bfloat16 l2 = __float2bfloat16(v.z - __bfloat162float(h2));
            __nv_bfloat16 l3 = __float2bfloat16(v.w - __bfloat162float(h3));
            uint32_t off = (uint32_t)(r * AS + col * 2);
            *(uint2*)(smc + SM_A_HI + off) = make_uint2(packbf(h0, h1), packbf(h2, h3));
            *(uint2*)(smc + SM_A_LO + off) = make_uint2(packbf(l0, l1), packbf(l2, l3));
        }
        // B chunk: pre-split bf16 (192 rows x 64 cols)
#pragma unroll
        for (int it = 0; it < 12; it++) {
            int i = tid + it * 256;         // 0..3071
            int r = i >> 4, col = (i & 15) * 4;
            size_t src = (size_t)r * E_DIM + k0 + col;
            uint32_t off = (uint32_t)(r * AS + col * 2);
            *(uint2*)(smc + SM_B_HI + off) = *(const uint2*)&g_wcat_hi[src];
            *(uint2*)(smc + SM_B_LO + off) = *(const uint2*)&g_wcat_lo[src];
        }
        __syncthreads();

#pragma unroll
        for (int ks = 0; ks < 4; ks++) {
            const uint32_t kb = (uint32_t)(ks * 32);
            uint32_t ahi[2][4], alo[2][4];
#pragma unroll
            for (int im = 0; im < 2; im++) {
                ldsm_x4(ahi[im], sb + SM_A_HI + aOff + im * 16 * AS + kb);
                ldsm_x4(alo[im], sb + SM_A_LO + aOff + im * 16 * AS + kb);
            }
            uint32_t bhi[6][2], blo[6][2];
#pragma unroll
            for (int j = 0; j < 3; j++) {
                uint32_t t[4];
                ldsm_x4(t, sb + SM_B_HI + bOff + j * 16 * AS + kb);
                bhi[2 * j][0] = t[0]; bhi[2 * j][1] = t[1];
                bhi[2 * j + 1][0] = t[2]; bhi[2 * j + 1][1] = t[3];
                ldsm_x4(t, sb + SM_B_LO + bOff + j * 16 * AS + kb);
                blo[2 * j][0] = t[0]; blo[2 * j][1] = t[1];
                blo[2 * j + 1][0] = t[2]; blo[2 * j + 1][1] = t[3];
            }
#pragma unroll
            for (int im = 0; im < 2; im++)
#pragma unroll
                for (int jn = 0; jn < 6; jn++) {
                    mma_bf16(acc[im][jn], ahi[im], bhi[jn]);
                    mma_bf16(acc[im][jn], ahi[im], blo[jn]);
                    mma_bf16(acc[im][jn], alo[im], bhi[jn]);
                }
        }
        __syncthreads();
    }

    // stage accumulators to smem: [64 rows][192 cols] fp32, stride STG_S
    float* stage = (float*)smc;
#pragma unroll
    for (int im = 0; im < 2; im++)
#pragma unroll
        for (int jn = 0; jn < 6; jn++) {
            int row = wm * 32 + im * 16 + (lane >> 2);
            int col = wn * 48 + jn * 8 + (lane & 3) * 2;
            stage[row * STG_S + col]           = acc[im][jn][0];
            stage[row * STG_S + col + 1]       = acc[im][jn][1];
            stage[(row + 8) * STG_S + col]     = acc[im][jn][2];
            stage[(row + 8) * STG_S + col + 1] = acc[im][jn][3];
        }
    __syncthreads();

    // LayerNorm epilogue: thread t<192 -> row = t&63, segment = t>>6
    if (tid < 192) {
        int row = tid & 63;
        int seg = tid >> 6;
        float f[64];
#pragma unroll
        for (int c = 0; c < 64; c++) f[c] = stage[row * STG_S + seg * 64 + c];
        if (seg < 2) {
            const float* gamma = (seg == 0) ? q_gamma : k_gamma;
            const float* beta  = (seg == 0) ? q_beta  : k_beta;
            float s = 0.f;
#pragma unroll
            for (int c = 0; c < 64; c++) s += f[c];
            float mu = s * (1.f / 64.f);
            float v2 = 0.f;
#pragma unroll
            for (int c = 0; c < 64; c++) { float d = f[c] - mu; v2 += d * d; }
            float rstd = rsqrtf(v2 * (1.f / 64.f) + 1e-5f);
#pragma unroll
            for (int c = 0; c < 64; c++) f[c] = (f[c] - mu) * rstd * gamma[c] + beta[c];
        }
        float* outg = (seg == 0) ? g_q : (seg == 1) ? g_k : g_v;
        size_t dst = (size_t)(m0 + row) * H_DIM;
#pragma unroll
        for (int c4 = 0; c4 < 16; c4++)
            *(float4*)&outg[dst + c4 * 4] =
                make_float4(f[c4 * 4], f[c4 * 4 + 1], f[c4 * 4 + 2], f[c4 * 4 + 3]);
    }
}

// ---------------------------------------------------------------------------
// Kernel 2: flash attention w/ fused Gaussian aug (unchanged from R2)
// ---------------------------------------------------------------------------
#define ATTN_SMEM_FLOATS (4 * 64 * 68 + 3 * 64)
#define ATTN_SMEM_BYTES  (ATTN_SMEM_FLOATS * 4)

__global__ __launch_bounds__(256) void attn_kernel(
    const float* __restrict__ w_sigma, const float* __restrict__ b_sigma,
    const float* __restrict__ w_alpha, const float* __restrict__ b_alpha,
    float* __restrict__ out)
{
    extern __shared__ float smf[];
    float* q_s = smf;
    float* k_s = q_s + 64 * 68;
    float* v_s = k_s + 64 * 68;
    float* p_s = v_s + 64 * 68;
    float* al_s = p_s + 64 * 68;
    float* ix_s = al_s + 64;
    float* iy_s = ix_s + 64;

    const int b   = blockIdx.y;
    const int q0  = blockIdx.x * 64;
    const int tid = threadIdx.x;
    const int ty  = tid >> 4, tx = tid & 15;
    const size_t base = (size_t)b * T_LEN * H_DIM;

#pragma unroll
    for (int i = 0; i < 4; i++) {
        int f4 = tid + i * 256;
        int r = f4 >> 4, c4 = f4 & 15;
        int qi = q0 + r;
        float4 qv = (qi < T_LEN) ? *(const float4*)&g_q[base + (size_t)qi * H_DIM + c4 * 4]
                                 : make_float4(0.f, 0.f, 0.f, 0.f);
        *(float4*)&q_s[r * 68 + c4 * 4] = qv;
    }
    __syncthreads();

    if (tid < 64) {
        int r = tid;
        int qi = q0 + r;
        if (qi >= 1 && qi < T_LEN) {
            float a = 0.f, s0 = 0.f, s1 = 0.f;
#pragma unroll 8
            for (int c = 0; c < 64; c++) {
                float qv = q_s[r * 68 + c];
                a  += qv * w_alpha[c];
                s0 += qv * w_sigma[c * 2 + 0];
                s1 += qv * w_sigma[c * 2 + 1];
            }
            a += b_alpha[0]; s0 += b_sigma[0]; s1 += b_sigma[1];
            float alpha = fmaxf(a, 0.f) + log1pf(expf(-fabsf(a)));
            float sx = 1.f / (1.f + expf(-s0));
            float sy = 1.f / (1.f + expf(-s1));
            al_s[r] = alpha;
            ix_s[r] = 0.5f / (sx * sx);
            iy_s[r] = 0.5f / (sy * sy);
        } else {
            al_s[r] = 0.f; ix_s[r] = 0.f; iy_s[r] = 0.f;
        }
    }
    __syncthreads();

    float m_i[4], l_i[4];
    float alr[4], ixr[4], iyr[4], qgx[4], qgy[4];
    bool  qaug[4];
#pragma unroll
    for (int iq = 0; iq < 4; iq++) {
        int r = ty * 4 + iq;
        int qi = q0 + r;
        m_i[iq] = -1e30f;
        l_i[iq] = 0.f;
        alr[iq] = al_s[r]; ixr[iq] = ix_s[r]; iyr[iq] = iy_s[r];
        qaug[iq] = (qi >= 1 && qi < T_LEN);
        int gq = (qi >= 1) ? qi - 1 : 0;
        qgx[iq] = (float)(gq % GW);
        qgy[iq] = (float)(gq / GW);
    }

    float oacc[4][4];
#pragma unroll
    for (int i = 0; i < 4; i++)
#pragma unroll
        for (int j = 0; j < 4; j++) oacc[i][j] = 0.f;

    for (int k0 = 0; k0 < T_LEN; k0 += 64) {
#pragma unroll
        for (int i = 0; i < 4; i++) {
            int f4 = tid + i * 256;
            int r = f4 >> 4, c4 = f4 & 15;
            int ki = k0 + r;
            float4 kv = make_float4(0.f, 0.f, 0.f, 0.f);
            float4 vv = kv;
            if (ki < T_LEN) {
                kv = *(const float4*)&g_k[base + (size_t)ki * H_DIM + c4 * 4];
                vv = *(const float4*)&g_v[base + (size_t)ki * H_DIM + c4 * 4];
            }
            *(float4*)&k_s[r * 68 + c4 * 4] = kv;
            *(float4*)&v_s[r * 68 + c4 * 4] = vv;
        }
        __syncthreads();

        float s[4][4];
#pragma unroll
        for (int i = 0; i < 4; i++)
#pragma unroll
            for (int j = 0; j < 4; j++) s[i][j] = 0.f;
#pragma unroll 4
        for (int j4 = 0; j4 < 16; j4++) {
            float4 qv[4], kv[4];
#pragma unroll
            for (int i = 0; i < 4; i++)
                qv[i] = *(const float4*)&q_s[(ty * 4 + i) * 68 + j4 * 4];
#pragma unroll
            for (int i = 0; i < 4; i++)
                kv[i] = *(const float4*)&k_s[(tx * 4 + i) * 68 + j4 * 4];
#pragma unroll
            for (int iq = 0; iq < 4; iq++)
#pragma unroll
                for (int ik = 0; ik < 4; ik++)
                    s[iq][ik] += qv[iq].x * kv[ik].x + qv[iq].y * kv[ik].y +
                                 qv[iq].z * kv[ik].z + qv[iq].w * kv[ik].w;
        }

#pragma unroll
        for (int ik = 0; ik < 4; ik++) {
            int ki = k0 + tx * 4 + ik;
            bool kvalid = (ki < T_LEN);
            bool kaug = (ki >= 1) && kvalid;
            int g = kaug ? ki - 1 : 0;
            float kgx = (float)(g % GW);
            float kgy = (float)(g / GW);
#pragma unroll
            for (int iq = 0; iq < 4; iq++) {
                float val = s[iq][ik];
                if (kaug && qaug[iq]) {
                    float dgx = qgx[iq] - kgx;
                    float dgy = qgy[iq] - kgy;
                    val += alr[iq] * __expf(-dgx * dgx * ixr[iq] - dgy * dgy * iyr[iq]);
                }
                val *= 0.125f;
                if (!kvalid) val = -1e30f;
                s[iq][ik] = val;
            }
        }

        float mloc[4];
#pragma unroll
        for (int iq = 0; iq < 4; iq++)
            mloc[iq] = fmaxf(fmaxf(s[iq][0], s[iq][1]), fmaxf(s[iq][2], s[iq][3]));
#pragma unroll
        for (int o = 8; o >= 1; o >>= 1)
#pragma unroll
            for (int iq = 0; iq < 4; iq++)
                mloc[iq] = fmaxf(mloc[iq], __shfl_xor_sync(0xffffffffu, mloc[iq], o));

        float rs[4];
#pragma unroll
        for (int iq = 0; iq < 4; iq++) {
            float mnew = fmaxf(m_i[iq], mloc[iq]);
            float scf = __expf(m_i[iq] - mnew);
            m_i[iq] = mnew;
            float sum = 0.f;
#pragma unroll
            for (int ik = 0; ik < 4; ik++) {
                float p = __expf(s[iq][ik] - mnew);
                s[iq][ik] = p;
                sum += p;
            }
            rs[iq] = sum;
            l_i[iq] *= scf;
#pragma unroll
            for (int ih = 0; ih < 4; ih++) oacc[iq][ih] *= scf;
        }
#pragma unroll
        for (int o = 8; o >= 1; o >>= 1)
#pragma unroll
            for (int iq = 0; iq < 4; iq++)
                rs[iq] += __shfl_xor_sync(0xffffffffu, rs[iq], o);
#pragma unroll
        for (int iq = 0; iq < 4; iq++) l_i[iq] += rs[iq];

#pragma unroll
        for (int iq = 0; iq < 4; iq++)
            *(float4*)&p_s[(ty * 4 + iq) * 68 + tx * 4] =
                make_float4(s[iq][0], s[iq][1], s[iq][2], s[iq][3]);
        __syncthreads();

#pragma unroll 2
        for (int kc4 = 0; kc4 < 16; kc4++) {
            float4 pr[4], vv[4];
#pragma unroll
            for (int iq = 0; iq < 4; iq++)
                pr[iq] = *(const float4*)&p_s[(ty * 4 + iq) * 68 + kc4 * 4];
#pragma unroll
            for (int j = 0; j < 4; j++)
                vv[j] = *(const float4*)&v_s[(kc4 * 4 + j) * 68 + tx * 4];
#pragma unroll
            for (int iq = 0; iq < 4; iq++) {
                oacc[iq][0] += pr[iq].x * vv[0].x + pr[iq].y * vv[1].x +
                               pr[iq].z * vv[2].x + pr[iq].w * vv[3].x;
                oacc[iq][1] += pr[iq].x * vv[0].y + pr[iq].y * vv[1].y +
                               pr[iq].z * vv[2].y + pr[iq].w * vv[3].y;
                oacc[iq][2] += pr[iq].x * vv[0].z + pr[iq].y * vv[1].z +
                               pr[iq].z * vv[2].z + pr[iq].w * vv[3].z;
                oacc[iq][3] += pr[iq].x * vv[0].w + pr[iq].y * vv[1].w +
                               pr[iq].z * vv[2].w + pr[iq].w * vv[3].w;
            }
        }
        __syncthreads();
    }

#pragma unroll
    for (int iq = 0; iq < 4; iq++) {
        int r = ty * 4 + iq;
        int qi = q0 + r;
        if (qi < T_LEN) {
            float inv = 1.f / l_i[iq];
            float4 o;
            o.x = oacc[iq][0] * inv;
            o.y = oacc[iq][1] * inv;
            o.z = oacc[iq][2] * inv;
            o.w = oacc[iq][3] * inv;
            *(float4*)&out[base + (size_t)qi * H_DIM + tx * 4] = o;
        }
    }
}

// ---------------------------------------------------------------------------
extern "C" void kernel_launch(void* const* d_in, const int* in_sizes, int n_in,
                              void* d_out, int out_size)
{
    const float* x       = (const float*)d_in[0];
    const float* w_q     = (const float*)d_in[1];
    const float* w_k     = (const float*)d_in[2];
    const float* w_v     = (const float*)d_in[3];
    const float* q_gamma = (const float*)d_in[4];
    const float* q_beta  = (const float*)d_in[5];
    const float* k_gamma = (const float*)d_in[6];
    const float* k_beta  = (const float*)d_in[7];
    const float* w_sigma = (const float*)d_in[8];
    const float* b_sigma = (const float*)d_in[9];
    const float* w_alpha = (const float*)d_in[10];
    const float* b_alpha = (const float*)d_in[11];
    float* out = (float*)d_out;

    prep_w_kernel<<<(192 * E_DIM + 255) / 256, 256>>>(w_q, w_k, w_v);

    cudaFuncSetAttribute(qkv_mma_kernel, cudaFuncAttributeMaxDynamicSharedMemorySize, SM_TOTAL);
    qkv_mma_kernel<<<M_ROWS / 64, 256, SM_TOTAL>>>(x, q_gamma, q_beta, k_gamma, k_beta);

    cudaFuncSetAttribute(attn_kernel, cudaFuncAttributeMaxDynamicSharedMemorySize, ATTN_SMEM_BYTES);
    dim3 grid2((T_LEN + 63) / 64, B_SZ);
    attn_kernel<<<grid2, 256, ATTN_SMEM_BYTES>>>(w_sigma, b_sigma, w_alpha, b_alpha, out);
}

// round 5
// speedup vs baseline: 1.3369x; 1.3369x over previous
#include <cuda_runtime.h>
#include <math.h>

#define M_ROWS 36928   // B*T = 64*577
#define E_DIM  768
#define H_DIM  64
#define T_LEN  577
#define B_SZ   64
#define GW     24

// scratch (static device arrays; no allocation)
__device__ float g_q[M_ROWS * H_DIM];
__device__ float g_k[M_ROWS * H_DIM];
__device__ float g_v[M_ROWS * H_DIM];

// ---------------------------------------------------------------------------
// Kernel 1: fused QKV projection + LayerNorm epilogue (R1 FFMA version —
// measured at the fp32 FFMA roofline)
// ---------------------------------------------------------------------------
__global__ __launch_bounds__(256) void qkv_ln_kernel(
    const float* __restrict__ x,
    const float* __restrict__ w_q, const float* __restrict__ w_k, const float* __restrict__ w_v,
    const float* __restrict__ q_gamma, const float* __restrict__ q_beta,
    const float* __restrict__ k_gamma, const float* __restrict__ k_beta)
{
    const int which = blockIdx.y;
    const float* __restrict__ w = (which == 0) ? w_q : (which == 1) ? w_k : w_v;
    float* __restrict__ outg = (which == 0) ? g_q : (which == 1) ? g_k : g_v;
    const float* __restrict__ gamma = (which == 0) ? q_gamma : k_gamma;
    const float* __restrict__ beta  = (which == 0) ? q_beta  : k_beta;

    __shared__ float smem[128 * 65];
    __shared__ float mu_s[128], rstd_s[128];
    float* x_s = smem;               // [16][132]
    float* w_s = smem + 16 * 132;    // [16][68]

    const int m0  = blockIdx.x * 128;
    const int tid = threadIdx.x;
    const int ty  = tid >> 4;
    const int tx  = tid & 15;

    float acc[8][4];
#pragma unroll
    for (int i = 0; i < 8; i++)
#pragma unroll
        for (int j = 0; j < 4; j++) acc[i][j] = 0.f;

    for (int k0 = 0; k0 < E_DIM; k0 += 16) {
#pragma unroll
        for (int i = tid; i < 128 * 16; i += 256) {
            int r = i >> 4, c = i & 15;
            int m = m0 + r;
            float vx = (m < M_ROWS) ? x[(size_t)m * E_DIM + k0 + c] : 0.f;
            x_s[c * 132 + r] = vx;
        }
#pragma unroll
        for (int i = tid; i < 16 * 64; i += 256) {
            int r = i >> 6, c = i & 63;
            w_s[r * 68 + c] = w[(k0 + r) * H_DIM + c];
        }
        __syncthreads();
#pragma unroll
        for (int j = 0; j < 16; j++) {
            float4 xv0 = *(const float4*)&x_s[j * 132 + ty * 8];
            float4 xv1 = *(const float4*)&x_s[j * 132 + ty * 8 + 4];
            float4 wv  = *(const float4*)&w_s[j * 68 + tx * 4];
            float xr[8] = {xv0.x, xv0.y, xv0.z, xv0.w, xv1.x, xv1.y, xv1.z, xv1.w};
            float wr[4] = {wv.x, wv.y, wv.z, wv.w};
#pragma unroll
            for (int i = 0; i < 8; i++)
#pragma unroll
                for (int jj = 0; jj < 4; jj++)
                    acc[i][jj] += xr[i] * wr[jj];
        }
        __syncthreads();
    }

    float* out_s = smem;   // [128][65]
#pragma unroll
    for (int i = 0; i < 8; i++)
#pragma unroll
        for (int jj = 0; jj < 4; jj++)
            out_s[(ty * 8 + i) * 65 + tx * 4 + jj] = acc[i][jj];
    __syncthreads();

    if (which < 2) {
        if (tid < 128) {
            int r = tid;
            if (m0 + r < M_ROWS) {
                float s = 0.f;
#pragma unroll 8
                for (int c = 0; c < 64; c++) s += out_s[r * 65 + c];
                float mu = s * (1.f / 64.f);
                float v2 = 0.f;
#pragma unroll 8
                for (int c = 0; c < 64; c++) {
                    float d = out_s[r * 65 + c] - mu;
                    v2 += d * d;
                }
                mu_s[r]   = mu;
                rstd_s[r] = rsqrtf(v2 * (1.f / 64.f) + 1e-5f);
            }
        }
        __syncthreads();
    }

#pragma unroll
    for (int i = tid; i < 128 * 64; i += 256) {
        int r = i >> 6, c = i & 63;
        int m = m0 + r;
        if (m < M_ROWS) {
            float val = out_s[r * 65 + c];
            if (which < 2)
                val = (val - mu_s[r]) * rstd_s[r] * gamma[c] + beta[c];
            outg[(size_t)m * H_DIM + c] = val;
        }
    }
}

// ---------------------------------------------------------------------------
// Kernel 2 (v3): flash attention, QT=128 KT=128, 256 threads, 8x8 thread tiles
// ty = tid>>4 (16 groups x 8 q rows), tx = tid&15 (16 lanes)
// sim: thread owns 8 q x 8 k (k strided: ki = k0 + tx + 16*ik)
// PV : thread owns 8 q x 4 h (h = tx*4..tx*4+3)
// 1/sqrt(H) folded into q and alpha.
// ---------------------------------------------------------------------------
#define QT 128
#define KT 128
#define QS 68     // q/k/v row stride (floats); 68 mod 32 == 4 -> 2-wf k loads
#define PS 132    // p row stride
#define ATTN_SMEM_FLOATS (QT*QS + KT*QS + KT*QS + QT*PS + 5*QT)
#define ATTN_SMEM_BYTES  (ATTN_SMEM_FLOATS * 4)

__global__ __launch_bounds__(256, 1) void attn_kernel(
    const float* __restrict__ w_sigma, const float* __restrict__ b_sigma,
    const float* __restrict__ w_alpha, const float* __restrict__ b_alpha,
    float* __restrict__ out)
{
    extern __shared__ float smf[];
    float* q_s  = smf;                  // [QT][QS]
    float* k_s  = q_s + QT * QS;        // [KT][QS]
    float* v_s  = k_s + KT * QS;        // [KT][QS]
    float* p_s  = v_s + KT * QS;        // [QT][PS]
    float* al_s = p_s + QT * PS;        // [QT] x5 param arrays
    float* ix_s = al_s + QT;
    float* iy_s = ix_s + QT;
    float* gx_s = iy_s + QT;
    float* gy_s = gx_s + QT;

    const int b   = blockIdx.y;
    const int q0  = blockIdx.x * QT;
    const int tid = threadIdx.x;
    const int ty  = tid >> 4, tx = tid & 15;
    const size_t base = (size_t)b * T_LEN * H_DIM;

    // load q tile, folding 0.125 = 1/sqrt(H) into q
#pragma unroll
    for (int i = 0; i < 8; i++) {
        int f4 = tid + i * 256;             // 0..2047
        int r = f4 >> 4, c4 = f4 & 15;
        int qi = q0 + r;
        float4 qv = make_float4(0.f, 0.f, 0.f, 0.f);
        if (qi < T_LEN) qv = *(const float4*)&g_q[base + (size_t)qi * H_DIM + c4 * 4];
        qv.x *= 0.125f; qv.y *= 0.125f; qv.z *= 0.125f; qv.w *= 0.125f;
        *(float4*)&q_s[r * QS + c4 * 4] = qv;
    }
    __syncthreads();

    // per-q-row augmentation params (alpha pre-scaled by 0.125)
    if (tid < QT) {
        int r = tid;
        int qi = q0 + r;
        if (qi >= 1 && qi < T_LEN) {
            float a = 0.f, s0 = 0.f, s1 = 0.f;
#pragma unroll 8
            for (int c = 0; c < 64; c++) {
                float qv = q_s[r * QS + c] * 8.f;   // undo 0.125 fold
                a  += qv * w_alpha[c];
                s0 += qv * w_sigma[c * 2 + 0];
                s1 += qv * w_sigma[c * 2 + 1];
            }
            a += b_alpha[0]; s0 += b_sigma[0]; s1 += b_sigma[1];
            float alpha = fmaxf(a, 0.f) + log1pf(expf(-fabsf(a)));
            float sx = 1.f / (1.f + expf(-s0));
            float sy = 1.f / (1.f + expf(-s1));
            al_s[r] = alpha * 0.125f;
            ix_s[r] = 0.5f / (sx * sx);
            iy_s[r] = 0.5f / (sy * sy);
            int gq = qi - 1;
            gx_s[r] = (float)(gq % GW);
            gy_s[r] = (float)(gq / GW);
        } else {
            al_s[r] = 0.f; ix_s[r] = 0.f; iy_s[r] = 0.f;
            gx_s[r] = 0.f; gy_s[r] = 0.f;
        }
    }
    __syncthreads();

    // per-row register state (replicated across 16 tx lanes)
    float m_i[8], l_i[8], alr[8], ixr[8], iyr[8], qgx[8], qgy[8];
#pragma unroll
    for (int iq = 0; iq < 8; iq++) {
        int r = ty * 8 + iq;
        m_i[iq] = -1e30f;
        l_i[iq] = 0.f;
        alr[iq] = al_s[r]; ixr[iq] = ix_s[r]; iyr[iq] = iy_s[r];
        qgx[iq] = gx_s[r]; qgy[iq] = gy_s[r];
    }

    float oacc[8][4];
#pragma unroll
    for (int i = 0; i < 8; i++)
#pragma unroll
        for (int j = 0; j < 4; j++) oacc[i][j] = 0.f;

    for (int k0 = 0; k0 < T_LEN; k0 += KT) {
        // load K/V tile (coalesced float4)
#pragma unroll
        for (int i = 0; i < 8; i++) {
            int f4 = tid + i * 256;
            int r = f4 >> 4, c4 = f4 & 15;
            int ki = k0 + r;
            float4 kv = make_float4(0.f, 0.f, 0.f, 0.f);
            float4 vv = kv;
            if (ki < T_LEN) {
                kv = *(const float4*)&g_k[base + (size_t)ki * H_DIM + c4 * 4];
                vv = *(const float4*)&g_v[base + (size_t)ki * H_DIM + c4 * 4];
            }
            *(float4*)&k_s[r * QS + c4 * 4] = kv;
            *(float4*)&v_s[r * QS + c4 * 4] = vv;
        }
        __syncthreads();

        // sim: 8q x 8k per thread, k rows strided (tx + 16*ik)
        float s[8][8];
#pragma unroll
        for (int i = 0; i < 8; i++)
#pragma unroll
            for (int j = 0; j < 8; j++) s[i][j] = 0.f;

#pragma unroll 2
        for (int j4 = 0; j4 < 16; j4++) {
            float4 qv[8], kv[8];
#pragma unroll
            for (int i = 0; i < 8; i++)
                qv[i] = *(const float4*)&q_s[(ty * 8 + i) * QS + j4 * 4];
#pragma unroll
            for (int j = 0; j < 8; j++)
                kv[j] = *(const float4*)&k_s[(tx + 16 * j) * QS + j4 * 4];
#pragma unroll
            for (int iq = 0; iq < 8; iq++)
#pragma unroll
                for (int ik = 0; ik < 8; ik++)
                    s[iq][ik] += qv[iq].x * kv[ik].x + qv[iq].y * kv[ik].y +
                                 qv[iq].z * kv[ik].z + qv[iq].w * kv[ik].w;
        }

        // Gaussian augmentation + mask (scale already folded into q / alpha)
#pragma unroll
        for (int ik = 0; ik < 8; ik++) {
            int ki = k0 + tx + 16 * ik;
            bool kvalid = (ki < T_LEN);
            bool kaug = (ki >= 1) && kvalid;
            int g = kaug ? ki - 1 : 0;
            float kgx = (float)(g % GW);
            float kgy = (float)(g / GW);
#pragma unroll
            for (int iq = 0; iq < 8; iq++) {
                float val = s[iq][ik];
                if (kaug) {
                    float dgx = qgx[iq] - kgx;
                    float dgy = qgy[iq] - kgy;
                    val += alr[iq] * __expf(-dgx * dgx * ixr[iq] - dgy * dgy * iyr[iq]);
                }
                if (!kvalid) val = -1e30f;
                s[iq][ik] = val;
            }
        }

        // register softmax: reduce over 16 tx lanes (xor 1,2,4,8 = lane bits 0-3)
        float mloc[8];
#pragma unroll
        for (int iq = 0; iq < 8; iq++) {
            float mm = s[iq][0];
#pragma unroll
            for (int ik = 1; ik < 8; ik++) mm = fmaxf(mm, s[iq][ik]);
            mloc[iq] = mm;
        }
#pragma unroll
        for (int o = 8; o >= 1; o >>= 1)
#pragma unroll
            for (int iq = 0; iq < 8; iq++)
                mloc[iq] = fmaxf(mloc[iq], __shfl_xor_sync(0xffffffffu, mloc[iq], o));

        float rs[8];
#pragma unroll
        for (int iq = 0; iq < 8; iq++) {
            float mnew = fmaxf(m_i[iq], mloc[iq]);
            float scf = __expf(m_i[iq] - mnew);
            m_i[iq] = mnew;
            float sum = 0.f;
#pragma unroll
            for (int ik = 0; ik < 8; ik++) {
                float p = __expf(s[iq][ik] - mnew);
                s[iq][ik] = p;
                sum += p;
            }
            rs[iq] = sum;
            l_i[iq] *= scf;
#pragma unroll
            for (int ih = 0; ih < 4; ih++) oacc[iq][ih] *= scf;
        }
#pragma unroll
        for (int o = 8; o >= 1; o >>= 1)
#pragma unroll
            for (int iq = 0; iq < 8; iq++)
                rs[iq] += __shfl_xor_sync(0xffffffffu, rs[iq], o);
#pragma unroll
        for (int iq = 0; iq < 8; iq++) l_i[iq] += rs[iq];

        // stage P (exp'd) to smem: scalar stores at strided k positions
#pragma unroll
        for (int iq = 0; iq < 8; iq++)
#pragma unroll
            for (int ik = 0; ik < 8; ik++)
                p_s[(ty * 8 + iq) * PS + tx + 16 * ik] = s[iq][ik];
        __syncthreads();

        // P @ V: thread computes 8q x 4h (h = tx*4..tx*4+3)
#pragma unroll 2
        for (int kc4 = 0; kc4 < KT / 4; kc4++) {
            float4 pr[8];
#pragma unroll
            for (int iq = 0; iq < 8; iq++)
                pr[iq] = *(const float4*)&p_s[(ty * 8 + iq) * PS + kc4 * 4];
            float4 vv[4];
#pragma unroll
            for (int j = 0; j < 4; j++)
                vv[j] = *(const float4*)&v_s[(kc4 * 4 + j) * QS + tx * 4];
#pragma unroll
            for (int iq = 0; iq < 8; iq++) {
                oacc[iq][0] += pr[iq].x * vv[0].x + pr[iq].y * vv[1].x +
                               pr[iq].z * vv[2].x + pr[iq].w * vv[3].x;
                oacc[iq][1] += pr[iq].x * vv[0].y + pr[iq].y * vv[1].y +
                               pr[iq].z * vv[2].y + pr[iq].w * vv[3].y;
                oacc[iq][2] += pr[iq].x * vv[0].z + pr[iq].y * vv[1].z +
                               pr[iq].z * vv[2].z + pr[iq].w * vv[3].z;
                oacc[iq][3] += pr[iq].x * vv[0].w + pr[iq].y * vv[1].w +
                               pr[iq].z * vv[2].w + pr[iq].w * vv[3].w;
            }
        }
        __syncthreads();
    }

    // final normalize + write (h cols tx*4..tx*4+3)
#pragma unroll
    for (int iq = 0; iq < 8; iq++) {
        int r = ty * 8 + iq;
        int qi = q0 + r;
        if (qi < T_LEN) {
            float inv = 1.f / l_i[iq];
            float4 o;
            o.x = oacc[iq][0] * inv;
            o.y = oacc[iq][1] * inv;
            o.z = oacc[iq][2] * inv;
            o.w = oacc[iq][3] * inv;
            *(float4*)&out[base + (size_t)qi * H_DIM + tx * 4] = o;
        }
    }
}

// ---------------------------------------------------------------------------
extern "C" void kernel_launch(void* const* d_in, const int* in_sizes, int n_in,
                              void* d_out, int out_size)
{
    const float* x       = (const float*)d_in[0];
    const float* w_q     = (const float*)d_in[1];
    const float* w_k     = (const float*)d_in[2];
    const float* w_v     = (const float*)d_in[3];
    const float* q_gamma = (const float*)d_in[4];
    const float* q_beta  = (const float*)d_in[5];
    const float* k_gamma = (const float*)d_in[6];
    const float* k_beta  = (const float*)d_in[7];
    const float* w_sigma = (const float*)d_in[8];
    const float* b_sigma = (const float*)d_in[9];
    const float* w_alpha = (const float*)d_in[10];
    const float* b_alpha = (const float*)d_in[11];
    float* out = (float*)d_out;

    dim3 grid1((M_ROWS + 127) / 128, 3);
    qkv_ln_kernel<<<grid1, 256>>>(x, w_q, w_k, w_v, q_gamma, q_beta, k_gamma, k_beta);

    cudaFuncSetAttribute(attn_kernel, cudaFuncAttributeMaxDynamicSharedMemorySize,
                         ATTN_SMEM_BYTES);
    dim3 grid2((T_LEN + QT - 1) / QT, B_SZ);
    attn_kernel<<<grid2, 256, ATTN_SMEM_BYTES>>>(w_sigma, b_sigma, w_alpha, b_alpha, out);
}